// round 7
// baseline (speedup 1.0000x reference)
#include <cuda_runtime.h>

#define N_NODES 100000
#define N_EDGES 1600000
#define F 128
#define ROWS_PER_WARP 2
#define WARPS_PER_BLK 16
#define THREADS_PER_BLK (WARPS_PER_BLK * 32)
#define LAYER_GRID 148
#define NGRP (N_NODES / ROWS_PER_WARP)   // 50000 exact

// dup-staged T: each row stored as 256 floats (each value twice)
#define TROW 256
// smem: W (128*128) + bias (128) + T (16 warps * 2 bufs * 2 rows * 256)
#define SMEM_FLOATS (F * F + F + WARPS_PER_BLK * 2 * ROWS_PER_WARP * TROW)
#define SMEM_BYTES (SMEM_FLOATS * 4)   // 131584 B -> 1 CTA/SM

typedef unsigned long long u64;

__device__ __forceinline__ void fma2(u64& d, u64 a, u64 b) {
    asm("fma.rn.f32x2 %0, %1, %2, %0;" : "+l"(d) : "l"(a), "l"(b));
}
__device__ __forceinline__ u64 pk2(float lo, float hi) {
    u64 r; asm("mov.b64 %0, {%1, %2};" : "=l"(r) : "f"(lo), "f"(hi)); return r;
}
__device__ __forceinline__ void upk2(u64 v, float& lo, float& hi) {
    asm("mov.b64 {%0, %1}, %2;" : "=f"(lo), "=f"(hi) : "l"(v));
}

// ---------------- scratch (no allocations allowed) ----------------
__device__ int   g_counts[N_NODES];
__device__ int   g_off[N_NODES + 1];
__device__ int   g_cursor[N_NODES];
__device__ int   g_bsum[128];
__device__ float g_inv[N_NODES];
__device__ int   g_csr[N_EDGES];
__device__ float g_h0[(size_t)N_NODES * F];
__device__ float g_h1[(size_t)N_NODES * F];

// ---------------- preprocessing: build CSR by dst ----------------
__global__ void k_zero() {
    int i = blockIdx.x * blockDim.x + threadIdx.x;
    if (i < N_NODES) g_counts[i] = 0;
}

__global__ void k_hist(const int* __restrict__ dst) {
    int e = blockIdx.x * blockDim.x + threadIdx.x;
    if (e < N_EDGES) atomicAdd(&g_counts[dst[e]], 1);
}

__global__ void k_scan_part() {
    __shared__ int sh[1024];
    int t = threadIdx.x;
    int j = blockIdx.x * 1024 + t;
    int v = (j < N_NODES) ? g_counts[j] : 0;
    sh[t] = v;
    __syncthreads();
    for (int d = 1; d < 1024; d <<= 1) {
        int x = (t >= d) ? sh[t - d] : 0;
        __syncthreads();
        sh[t] += x;
        __syncthreads();
    }
    int incl = sh[t];
    if (j <= N_NODES) g_off[j] = incl - v;
    if (t == 1023) g_bsum[blockIdx.x] = incl;
}

__global__ void k_scan_top(int nblocks) {
    __shared__ int sh[128];
    int t = threadIdx.x;
    int v = (t < nblocks) ? g_bsum[t] : 0;
    sh[t] = v;
    __syncthreads();
    for (int d = 1; d < 128; d <<= 1) {
        int x = (t >= d) ? sh[t - d] : 0;
        __syncthreads();
        sh[t] += x;
        __syncthreads();
    }
    if (t < nblocks) g_bsum[t] = sh[t] - v;
}

__global__ void k_scan_add() {
    int j = blockIdx.x * blockDim.x + threadIdx.x;
    if (j <= N_NODES) {
        int o = g_off[j] + g_bsum[j >> 10];
        g_off[j] = o;
        if (j < N_NODES) {
            g_cursor[j] = o;
            int c = g_counts[j];
            g_inv[j] = 1.0f / (float)(c > 0 ? c : 1);
        }
    }
}

__global__ void k_scatter(const int* __restrict__ src, const int* __restrict__ dst) {
    int e = blockIdx.x * blockDim.x + threadIdx.x;
    if (e < N_EDGES) {
        int d = dst[e];
        int pos = atomicAdd(&g_cursor[d], 1);
        g_csr[pos] = src[e];
    }
}

// ---------------- fused layer: mean-agg + (h+agg)@W + b (+relu) ----------------
// Depth-2 pipeline, parity stagger, dup-staged T feeding FFMA2 gemm.
__global__ __launch_bounds__(THREADS_PER_BLK)
void k_layer(const float* __restrict__ hin, const float* __restrict__ Wg,
             const float* __restrict__ bias, float* __restrict__ hout,
             int do_relu) {
    extern __shared__ float smem[];
    float* sW = smem;                 // F*F
    float* sb = smem + F * F;         // F
    float* sT = sb + F;               // dup-staged activations

    int tid = threadIdx.x;
    for (int i = tid; i < (F * F) / 4; i += blockDim.x)
        ((float4*)sW)[i] = ((const float4*)Wg)[i];
    if (tid < F) sb[tid] = bias[tid];
    __syncthreads();

    int lane = tid & 31;
    int wId = tid >> 5;
    int gwarp = blockIdx.x * WARPS_PER_BLK + wId;
    int nwarps = gridDim.x * WARPS_PER_BLK;
    float* buf0 = sT + wId * (2 * ROWS_PER_WARP * TROW);
    float* buf1 = buf0 + ROWS_PER_WARP * TROW;
    float4 bv = ((const float4*)sb)[lane];
    u64 bA = pk2(bv.x, bv.y);
    u64 bB = pk2(bv.z, bv.w);

    // ---- aggregate + dup-stage t = h + mean_neighbors(h) ----
    auto agg = [&](int grp, float* buf) {
        int row0 = grp * ROWS_PER_WARP;
        __syncwarp();
        #pragma unroll 1
        for (int r = 0; r < ROWS_PER_WARP; ++r) {
            int row = row0 + r;
            int e = g_off[row];
            int e1 = g_off[row + 1];
            float4 acc = make_float4(0.f, 0.f, 0.f, 0.f);
            for (; e + 4 <= e1; e += 4) {
                int s0 = g_csr[e + 0], s1 = g_csr[e + 1];
                int s2 = g_csr[e + 2], s3 = g_csr[e + 3];
                float4 v0 = *(const float4*)(hin + (size_t)s0 * F + lane * 4);
                float4 v1 = *(const float4*)(hin + (size_t)s1 * F + lane * 4);
                float4 v2 = *(const float4*)(hin + (size_t)s2 * F + lane * 4);
                float4 v3 = *(const float4*)(hin + (size_t)s3 * F + lane * 4);
                acc.x += (v0.x + v1.x) + (v2.x + v3.x);
                acc.y += (v0.y + v1.y) + (v2.y + v3.y);
                acc.z += (v0.z + v1.z) + (v2.z + v3.z);
                acc.w += (v0.w + v1.w) + (v2.w + v3.w);
            }
            for (; e < e1; ++e) {
                int s = g_csr[e];
                float4 v = *(const float4*)(hin + (size_t)s * F + lane * 4);
                acc.x += v.x; acc.y += v.y; acc.z += v.z; acc.w += v.w;
            }
            float sc = g_inv[row];
            float4 hv = *(const float4*)(hin + (size_t)row * F + lane * 4);
            float4 t;
            t.x = fmaf(acc.x, sc, hv.x);
            t.y = fmaf(acc.y, sc, hv.y);
            t.z = fmaf(acc.z, sc, hv.z);
            t.w = fmaf(acc.w, sc, hv.w);
            // duplicate-stage: (t.x,t.x,t.y,t.y) (t.z,t.z,t.w,t.w)
            float* p = buf + r * TROW + lane * 8;
            *(float4*)(p + 0) = make_float4(t.x, t.x, t.y, t.y);
            *(float4*)(p + 4) = make_float4(t.z, t.z, t.w, t.w);
        }
        __syncwarp();
    };

    // ---- out = t @ W + b, FFMA2 with dup-pair operands from smem ----
    auto gemm = [&](int grp, float* buf) {
        int row0 = grp * ROWS_PER_WARP;
        __syncwarp();
        u64 oA[ROWS_PER_WARP], oB[ROWS_PER_WARP];
        #pragma unroll
        for (int r = 0; r < ROWS_PER_WARP; ++r) { oA[r] = bA; oB[r] = bB; }

        #pragma unroll 4
        for (int kk = 0; kk < F / 4; ++kk) {
            // weight rows: column-pair packed for free via LDS.128
            ulonglong2 w0 = ((const ulonglong2*)(sW + (4 * kk + 0) * F))[lane];
            ulonglong2 w1 = ((const ulonglong2*)(sW + (4 * kk + 1) * F))[lane];
            ulonglong2 w2 = ((const ulonglong2*)(sW + (4 * kk + 2) * F))[lane];
            ulonglong2 w3 = ((const ulonglong2*)(sW + (4 * kk + 3) * F))[lane];
            #pragma unroll
            for (int r = 0; r < ROWS_PER_WARP; ++r) {
                // dup-staged broadcast loads: {(a0,a0),(a1,a1)}, {(a2,a2),(a3,a3)}
                ulonglong2 u01 = *(const ulonglong2*)(buf + r * TROW + 8 * kk);
                ulonglong2 u23 = *(const ulonglong2*)(buf + r * TROW + 8 * kk + 4);
                fma2(oA[r], u01.x, w0.x); fma2(oB[r], u01.x, w0.y);
                fma2(oA[r], u01.y, w1.x); fma2(oB[r], u01.y, w1.y);
                fma2(oA[r], u23.x, w2.x); fma2(oB[r], u23.x, w2.y);
                fma2(oA[r], u23.y, w3.x); fma2(oB[r], u23.y, w3.y);
            }
        }

        #pragma unroll
        for (int r = 0; r < ROWS_PER_WARP; ++r) {
            float4 v;
            upk2(oA[r], v.x, v.y);
            upk2(oB[r], v.z, v.w);
            if (do_relu) {
                v.x = fmaxf(v.x, 0.f); v.y = fmaxf(v.y, 0.f);
                v.z = fmaxf(v.z, 0.f); v.w = fmaxf(v.w, 0.f);
            }
            *(float4*)(hout + (size_t)(row0 + r) * F + lane * 4) = v;
        }
        __syncwarp();
    };

    // ---- depth-2 pipeline with parity stagger ----
    int g = gwarp;
    if (g < NGRP) {
        agg(g, buf0);
        int prev = g;
        float* pbuf = buf0;
        float* cbuf = buf1;
        int odd = wId & 1;
        for (g += nwarps; g < NGRP; g += nwarps) {
            if (odd) {
                gemm(prev, pbuf);
                agg(g, cbuf);
            } else {
                agg(g, cbuf);
                gemm(prev, pbuf);
            }
            float* tmp = pbuf; pbuf = cbuf; cbuf = tmp;
            prev = g;
        }
        gemm(prev, pbuf);
    }
}

// ---------------- launch ----------------
extern "C" void kernel_launch(void* const* d_in, const int* in_sizes, int n_in,
                              void* d_out, int out_size) {
    const float* x  = (const float*)d_in[0];
    const float* W1 = (const float*)d_in[1];
    const float* b1 = (const float*)d_in[2];
    const float* W2 = (const float*)d_in[3];
    const float* b2 = (const float*)d_in[4];
    const float* W3 = (const float*)d_in[5];
    const float* b3 = (const float*)d_in[6];
    const int* esrc = (const int*)d_in[7];
    const int* edst = (const int*)d_in[8];
    float* out = (float*)d_out;

    cudaFuncSetAttribute(k_layer, cudaFuncAttributeMaxDynamicSharedMemorySize,
                         SMEM_BYTES);

    void *ph0 = nullptr, *ph1 = nullptr;
    cudaGetSymbolAddress(&ph0, g_h0);
    cudaGetSymbolAddress(&ph1, g_h1);
    float* h0 = (float*)ph0;
    float* h1 = (float*)ph1;

    int scan_blocks = (N_NODES + 1 + 1023) / 1024;  // 98
    k_zero<<<(N_NODES + 255) / 256, 256>>>();
    k_hist<<<(N_EDGES + 255) / 256, 256>>>(edst);
    k_scan_part<<<scan_blocks, 1024>>>();
    k_scan_top<<<1, 128>>>(scan_blocks);
    k_scan_add<<<(N_NODES + 1 + 255) / 256, 256>>>();
    k_scatter<<<(N_EDGES + 255) / 256, 256>>>(esrc, edst);

    k_layer<<<LAYER_GRID, THREADS_PER_BLK, SMEM_BYTES>>>(x,  W1, b1, h0, 1);
    k_layer<<<LAYER_GRID, THREADS_PER_BLK, SMEM_BYTES>>>(h0, W2, b2, h1, 1);
    k_layer<<<LAYER_GRID, THREADS_PER_BLK, SMEM_BYTES>>>(h1, W3, b3, out, 0);
}

// round 8
// speedup vs baseline: 1.1637x; 1.1637x over previous
#include <cuda_runtime.h>

#define N_NODES 100000
#define N_EDGES 1600000
#define F 128
#define ROWS_PER_WARP 4
#define WARPS_PER_BLK 8
#define THREADS_PER_BLK (WARPS_PER_BLK * 32)
#define LAYER_GRID 296
#define NGRP (N_NODES / ROWS_PER_WARP)   // 25000 exact

// smem: W (128*128) + bias (128) + t-stage (8 warps * 2 bufs * 4 rows * 128)
#define SMEM_FLOATS (F * F + F + WARPS_PER_BLK * 2 * ROWS_PER_WARP * F)
#define SMEM_BYTES (SMEM_FLOATS * 4)

// ---------------- scratch (no allocations allowed) ----------------
// NOTE: device globals are zero-initialized at module load. g_counts is
// re-zeroed at the tail of k_scatter each call, so every kernel_launch
// invocation (correctness run + every graph replay) starts from counts==0.
__device__ int   g_counts[N_NODES];
__device__ int   g_off[N_NODES + 1];
__device__ int   g_cursor[N_NODES];
__device__ float g_inv[N_NODES];
__device__ int   g_csr[N_EDGES];
__device__ float g_h0[(size_t)N_NODES * F];
__device__ float g_h1[(size_t)N_NODES * F];

// ---------------- preprocessing: build CSR by dst (3 launches) ----------------
__global__ void k_hist(const int* __restrict__ dst) {
    int e = blockIdx.x * blockDim.x + threadIdx.x;
    if (e < N_EDGES) atomicAdd(&g_counts[dst[e]], 1);
}

// Single-block exclusive scan over g_counts -> g_off/g_cursor/g_inv.
// 1024 threads, int4 per thread, 25 chunks of 4096, warp-shuffle scans.
__global__ void k_scan1() {
    __shared__ int wsum[32];
    __shared__ int base_sh;
    int tid = threadIdx.x;
    int lane = tid & 31;
    int wid = tid >> 5;
    if (tid == 0) base_sh = 0;
    __syncthreads();

    for (int base = 0; base < N_NODES; base += 4096) {
        int i = base + tid * 4;
        int4 v = make_int4(0, 0, 0, 0);
        if (i < N_NODES) v = *(const int4*)(g_counts + i);
        int s = v.x + v.y + v.z + v.w;

        // inclusive warp scan of s
        int incl = s;
        #pragma unroll
        for (int d = 1; d < 32; d <<= 1) {
            int x = __shfl_up_sync(0xffffffffu, incl, d);
            if (lane >= d) incl += x;
        }
        if (lane == 31) wsum[wid] = incl;
        __syncthreads();

        if (wid == 0) {
            int ws = wsum[lane];
            int wincl = ws;
            #pragma unroll
            for (int d = 1; d < 32; d <<= 1) {
                int x = __shfl_up_sync(0xffffffffu, wincl, d);
                if (lane >= d) wincl += x;
            }
            wsum[lane] = wincl - ws;   // exclusive warp offsets
        }
        __syncthreads();

        int chunk_base = base_sh;
        int pre = chunk_base + wsum[wid] + (incl - s);  // exclusive prefix
        if (i < N_NODES) {
            int e0 = pre;
            int e1 = e0 + v.x;
            int e2 = e1 + v.y;
            int e3 = e2 + v.z;
            *(int4*)(g_off + i)    = make_int4(e0, e1, e2, e3);
            *(int4*)(g_cursor + i) = make_int4(e0, e1, e2, e3);
            g_inv[i + 0] = 1.0f / (float)(v.x > 0 ? v.x : 1);
            g_inv[i + 1] = 1.0f / (float)(v.y > 0 ? v.y : 1);
            g_inv[i + 2] = 1.0f / (float)(v.z > 0 ? v.z : 1);
            g_inv[i + 3] = 1.0f / (float)(v.w > 0 ? v.w : 1);
        }
        __syncthreads();   // everyone has read base_sh
        if (tid == 1023) base_sh = chunk_base + wsum[31] + incl;
        __syncthreads();
    }
    if (tid == 0) g_off[N_NODES] = base_sh;
}

// scatter into CSR; also re-zero g_counts for the next invocation
__global__ void k_scatter(const int* __restrict__ src, const int* __restrict__ dst) {
    int i = blockIdx.x * blockDim.x + threadIdx.x;
    if (i < N_EDGES) {
        int d = dst[i];
        int pos = atomicAdd(&g_cursor[d], 1);
        g_csr[pos] = src[i];
    }
    if (i < N_NODES) g_counts[i] = 0;
}

// ---------------- fused layer: mean-agg + (h+agg)@W + b (+relu) ----------------
// Software-pipelined (depth 2) with parity stagger: even warps do
// [agg(next); gemm(cur)], odd warps do [gemm(cur); agg(next)].
__global__ __launch_bounds__(THREADS_PER_BLK)
void k_layer(const float* __restrict__ hin, const float* __restrict__ Wg,
             const float* __restrict__ bias, float* __restrict__ hout,
             int do_relu) {
    extern __shared__ float smem[];
    float* sW = smem;                 // F*F
    float* sb = smem + F * F;         // F
    float* sT = sb + F;               // WARPS_PER_BLK * 2 * ROWS_PER_WARP * F

    int tid = threadIdx.x;
    for (int i = tid; i < (F * F) / 4; i += blockDim.x)
        ((float4*)sW)[i] = ((const float4*)Wg)[i];
    if (tid < F) sb[tid] = bias[tid];
    __syncthreads();

    int lane = tid & 31;
    int wId = tid >> 5;
    int gwarp = blockIdx.x * WARPS_PER_BLK + wId;
    int nwarps = gridDim.x * WARPS_PER_BLK;
    float* buf0 = sT + wId * (2 * ROWS_PER_WARP * F);
    float* buf1 = buf0 + ROWS_PER_WARP * F;
    float4 bv = ((const float4*)sb)[lane];

    auto agg = [&](int grp, float* buf) {
        int row0 = grp * ROWS_PER_WARP;
        __syncwarp();
        #pragma unroll 1
        for (int r = 0; r < ROWS_PER_WARP; ++r) {
            int row = row0 + r;
            int e = g_off[row];
            int e1 = g_off[row + 1];
            float4 acc = make_float4(0.f, 0.f, 0.f, 0.f);
            for (; e + 4 <= e1; e += 4) {
                int s0 = g_csr[e + 0], s1 = g_csr[e + 1];
                int s2 = g_csr[e + 2], s3 = g_csr[e + 3];
                float4 v0 = *(const float4*)(hin + (size_t)s0 * F + lane * 4);
                float4 v1 = *(const float4*)(hin + (size_t)s1 * F + lane * 4);
                float4 v2 = *(const float4*)(hin + (size_t)s2 * F + lane * 4);
                float4 v3 = *(const float4*)(hin + (size_t)s3 * F + lane * 4);
                acc.x += (v0.x + v1.x) + (v2.x + v3.x);
                acc.y += (v0.y + v1.y) + (v2.y + v3.y);
                acc.z += (v0.z + v1.z) + (v2.z + v3.z);
                acc.w += (v0.w + v1.w) + (v2.w + v3.w);
            }
            for (; e < e1; ++e) {
                int s = g_csr[e];
                float4 v = *(const float4*)(hin + (size_t)s * F + lane * 4);
                acc.x += v.x; acc.y += v.y; acc.z += v.z; acc.w += v.w;
            }
            float sc = g_inv[row];
            float4 hv = *(const float4*)(hin + (size_t)row * F + lane * 4);
            float4 t;
            t.x = fmaf(acc.x, sc, hv.x);
            t.y = fmaf(acc.y, sc, hv.y);
            t.z = fmaf(acc.z, sc, hv.z);
            t.w = fmaf(acc.w, sc, hv.w);
            *(float4*)(buf + r * F + lane * 4) = t;
        }
        __syncwarp();
    };

    auto gemm = [&](int grp, float* buf) {
        int row0 = grp * ROWS_PER_WARP;
        __syncwarp();
        float4 o[ROWS_PER_WARP];
        #pragma unroll
        for (int r = 0; r < ROWS_PER_WARP; ++r) o[r] = bv;

        #pragma unroll 4
        for (int kk = 0; kk < F / 4; ++kk) {
            float4 w0 = ((const float4*)(sW + (4 * kk + 0) * F))[lane];
            float4 w1 = ((const float4*)(sW + (4 * kk + 1) * F))[lane];
            float4 w2 = ((const float4*)(sW + (4 * kk + 2) * F))[lane];
            float4 w3 = ((const float4*)(sW + (4 * kk + 3) * F))[lane];
            #pragma unroll
            for (int r = 0; r < ROWS_PER_WARP; ++r) {
                float4 a = *(const float4*)(buf + r * F + 4 * kk);  // broadcast
                o[r].x += a.x * w0.x; o[r].y += a.x * w0.y;
                o[r].z += a.x * w0.z; o[r].w += a.x * w0.w;
                o[r].x += a.y * w1.x; o[r].y += a.y * w1.y;
                o[r].z += a.y * w1.z; o[r].w += a.y * w1.w;
                o[r].x += a.z * w2.x; o[r].y += a.z * w2.y;
                o[r].z += a.z * w2.z; o[r].w += a.z * w2.w;
                o[r].x += a.w * w3.x; o[r].y += a.w * w3.y;
                o[r].z += a.w * w3.z; o[r].w += a.w * w3.w;
            }
        }

        #pragma unroll
        for (int r = 0; r < ROWS_PER_WARP; ++r) {
            float4 v = o[r];
            if (do_relu) {
                v.x = fmaxf(v.x, 0.f); v.y = fmaxf(v.y, 0.f);
                v.z = fmaxf(v.z, 0.f); v.w = fmaxf(v.w, 0.f);
            }
            *(float4*)(hout + (size_t)(row0 + r) * F + lane * 4) = v;
        }
        __syncwarp();
    };

    // ---- depth-2 pipeline with parity stagger ----
    int g = gwarp;
    if (g < NGRP) {
        agg(g, buf0);
        int prev = g;
        float* pbuf = buf0;
        float* cbuf = buf1;
        int odd = wId & 1;
        for (g += nwarps; g < NGRP; g += nwarps) {
            if (odd) {
                gemm(prev, pbuf);
                agg(g, cbuf);
            } else {
                agg(g, cbuf);
                gemm(prev, pbuf);
            }
            float* tmp = pbuf; pbuf = cbuf; cbuf = tmp;
            prev = g;
        }
        gemm(prev, pbuf);
    }
}

// ---------------- launch ----------------
extern "C" void kernel_launch(void* const* d_in, const int* in_sizes, int n_in,
                              void* d_out, int out_size) {
    const float* x  = (const float*)d_in[0];
    const float* W1 = (const float*)d_in[1];
    const float* b1 = (const float*)d_in[2];
    const float* W2 = (const float*)d_in[3];
    const float* b2 = (const float*)d_in[4];
    const float* W3 = (const float*)d_in[5];
    const float* b3 = (const float*)d_in[6];
    const int* esrc = (const int*)d_in[7];
    const int* edst = (const int*)d_in[8];
    float* out = (float*)d_out;

    cudaFuncSetAttribute(k_layer, cudaFuncAttributeMaxDynamicSharedMemorySize,
                         SMEM_BYTES);

    void *ph0 = nullptr, *ph1 = nullptr;
    cudaGetSymbolAddress(&ph0, g_h0);
    cudaGetSymbolAddress(&ph1, g_h1);
    float* h0 = (float*)ph0;
    float* h1 = (float*)ph1;

    // 3 preproc launches, then the 3 layer launches (indices 3..5 in-stream)
    k_hist<<<(N_EDGES + 255) / 256, 256>>>(edst);
    k_scan1<<<1, 1024>>>();
    k_scatter<<<(N_EDGES + 255) / 256, 256>>>(esrc, edst);

    k_layer<<<LAYER_GRID, THREADS_PER_BLK, SMEM_BYTES>>>(x,  W1, b1, h0, 1);
    k_layer<<<LAYER_GRID, THREADS_PER_BLK, SMEM_BYTES>>>(h0, W2, b2, h1, 1);
    k_layer<<<LAYER_GRID, THREADS_PER_BLK, SMEM_BYTES>>>(h1, W3, b3, out, 0);
}